// round 1
// baseline (speedup 1.0000x reference)
#include <cuda_runtime.h>
#include <math.h>

// Problem constants
#define B_ 8
#define T_ 4096
#define D_ 512
#define M_TOTAL (B_ * T_)          // 32768 rows
#define CHUNK 128
#define NCHUNK (T_ / CHUNK)        // 32 chunks per batch

// ---------------------------------------------------------------------------
// Scratch (static __device__ globals: no allocation allowed in kernel_launch)
// ---------------------------------------------------------------------------
__device__ float g_bufA[(size_t)M_TOTAL * D_];   // 64 MB
__device__ float g_bufB[(size_t)M_TOTAL * D_];   // 64 MB
__device__ float g_partial[B_ * NCHUNK * D_];    // 512 KB
__device__ float g_summ[B_ * D_];                // 16 KB

// ---------------------------------------------------------------------------
// Stage 1: causal running mean  (chunked scan, 3 kernels)
// ---------------------------------------------------------------------------
__global__ void chunk_sum_kernel(const float* __restrict__ dec) {
    int bc = blockIdx.x;                 // b * NCHUNK + c
    int b  = bc / NCHUNK, c = bc % NCHUNK;
    int d  = threadIdx.x;                // 0..511
    const float* p = dec + ((size_t)(b * T_ + c * CHUNK)) * D_ + d;
    float s = 0.f;
    #pragma unroll 8
    for (int t = 0; t < CHUNK; ++t) s += p[(size_t)t * D_];
    g_partial[(size_t)bc * D_ + d] = s;
}

__global__ void chunk_prefix_kernel() {
    int b = blockIdx.x, d = threadIdx.x;
    float run = 0.f;
    for (int c = 0; c < NCHUNK; ++c) {
        size_t idx = ((size_t)(b * NCHUNK + c)) * D_ + d;
        float v = g_partial[idx];
        g_partial[idx] = run;            // exclusive prefix
        run += v;
    }
}

__global__ void cum_mean_kernel(const float* __restrict__ dec) {
    int bc = blockIdx.x;
    int b  = bc / NCHUNK, c = bc % NCHUNK;
    int d  = threadIdx.x;
    size_t base = ((size_t)(b * T_ + c * CHUNK)) * D_ + d;
    float run = g_partial[(size_t)bc * D_ + d];
    for (int t = 0; t < CHUNK; ++t) {
        run += dec[base + (size_t)t * D_];
        g_bufA[base + (size_t)t * D_] = run / (float)(c * CHUNK + t + 1);
    }
}

// ---------------------------------------------------------------------------
// Stage 2: summ_proj = summarization @ W1   [8,512]x[512,512] (tiny)
// ---------------------------------------------------------------------------
__global__ void summ_proj_kernel(const float* __restrict__ summ,
                                 const float* __restrict__ W1) {
    int b = blockIdx.x, n = threadIdx.x;
    __shared__ float s[D_];
    s[n] = summ[b * D_ + n];
    __syncthreads();
    float acc = 0.f;
    #pragma unroll 8
    for (int k = 0; k < D_; ++k) acc += s[k] * W1[k * D_ + n];
    g_summ[b * D_ + n] = acc;
}

// ---------------------------------------------------------------------------
// Stage 3: the three big GEMMs [32768,512] @ [512,512], fused epilogues
//   MODE 0: C = tanh(A@W + bias)
//   MODE 1: C = summ_proj[row/T] - A@W
//   MODE 2: C = tanh(A@W + bias) + residual
// Classic 128x128x16 tile, 8x8 per thread, 256 threads.
// ---------------------------------------------------------------------------
#define BM 128
#define BN 128
#define BK 16
#define TM 8
#define TN 8

template <int MODE>
__global__ __launch_bounds__(256)
void gemm_kernel(const float* __restrict__ A, const float* __restrict__ W,
                 const float* __restrict__ bias, const float* __restrict__ extra,
                 float* __restrict__ C) {
    __shared__ float As[BK][BM + 4];
    __shared__ float Bs[BK][BN];

    const int tid = threadIdx.x;
    const int blockRow = blockIdx.y;
    const int blockCol = blockIdx.x;
    const int tr = tid / 16;             // 0..15 (row group)
    const int tc = tid % 16;             // 0..15 (col group)

    const int K = D_, N = D_;
    const int aRow0 = tid / 4;           // 0..63
    const int aCol  = (tid % 4) * 4;     // 0,4,8,12
    const int bRow0 = tid / 32;          // 0..7
    const int bCol  = (tid % 32) * 4;    // 0..124

    float acc[TM][TN];
    #pragma unroll
    for (int i = 0; i < TM; ++i)
        #pragma unroll
        for (int j = 0; j < TN; ++j) acc[i][j] = 0.f;

    for (int kt = 0; kt < K; kt += BK) {
        // Load A tile (transposed into As[k][m])
        #pragma unroll
        for (int i = 0; i < 2; ++i) {
            int row = aRow0 + i * 64;
            float4 v = *(const float4*)(A + (size_t)(blockRow * BM + row) * K + kt + aCol);
            As[aCol + 0][row] = v.x;
            As[aCol + 1][row] = v.y;
            As[aCol + 2][row] = v.z;
            As[aCol + 3][row] = v.w;
        }
        // Load B tile
        #pragma unroll
        for (int i = 0; i < 2; ++i) {
            int row = bRow0 + i * 8;
            *(float4*)(&Bs[row][bCol]) =
                *(const float4*)(W + (size_t)(kt + row) * N + blockCol * BN + bCol);
        }
        __syncthreads();

        #pragma unroll
        for (int k = 0; k < BK; ++k) {
            float ra[TM], rb[TN];
            #pragma unroll
            for (int i = 0; i < TM; ++i) ra[i] = As[k][tr * TM + i];
            #pragma unroll
            for (int j = 0; j < TN; ++j) rb[j] = Bs[k][tc * TN + j];
            #pragma unroll
            for (int i = 0; i < TM; ++i)
                #pragma unroll
                for (int j = 0; j < TN; ++j)
                    acc[i][j] = fmaf(ra[i], rb[j], acc[i][j]);
        }
        __syncthreads();
    }

    #pragma unroll
    for (int i = 0; i < TM; ++i) {
        int row = blockRow * BM + tr * TM + i;
        #pragma unroll
        for (int j = 0; j < TN; ++j) {
            int col = blockCol * BN + tc * TN + j;
            float v = acc[i][j];
            if (MODE == 0) {
                v = tanhf(v + bias[col]);
            } else if (MODE == 1) {
                v = extra[(row / T_) * D_ + col] - v;
            } else {
                v = tanhf(v + bias[col]) + extra[(size_t)row * D_ + col];
            }
            C[(size_t)row * D_ + col] = v;
        }
    }
}

// ---------------------------------------------------------------------------
// Stage 4: LayerNorm over last dim (D=512), one block per row
// ---------------------------------------------------------------------------
__global__ __launch_bounds__(256)
void layernorm_kernel(const float* __restrict__ X,
                      const float* __restrict__ gamma,
                      const float* __restrict__ beta,
                      float* __restrict__ out) {
    int row = blockIdx.x;
    const float* x = X + (size_t)row * D_;
    int tid = threadIdx.x;               // 256 threads, 2 elems each

    float v0 = x[tid];
    float v1 = x[tid + 256];
    float s  = v0 + v1;
    float sq = v0 * v0 + v1 * v1;

    __shared__ float redS[8], redQ[8];
    #pragma unroll
    for (int o = 16; o > 0; o >>= 1) {
        s  += __shfl_down_sync(0xffffffffu, s, o);
        sq += __shfl_down_sync(0xffffffffu, sq, o);
    }
    if ((tid & 31) == 0) { redS[tid >> 5] = s; redQ[tid >> 5] = sq; }
    __syncthreads();
    if (tid < 32) {
        float a = (tid < 8) ? redS[tid] : 0.f;
        float b = (tid < 8) ? redQ[tid] : 0.f;
        #pragma unroll
        for (int o = 4; o > 0; o >>= 1) {
            a += __shfl_down_sync(0xffffffffu, a, o);
            b += __shfl_down_sync(0xffffffffu, b, o);
        }
        if (tid == 0) { redS[0] = a; redQ[0] = b; }
    }
    __syncthreads();

    float mu   = redS[0] * (1.0f / D_);
    float var  = redQ[0] * (1.0f / D_) - mu * mu;
    float rstd = rsqrtf(var + 1e-6f);

    float* o = out + (size_t)row * D_;
    o[tid]       = (v0 - mu) * rstd * gamma[tid]       + beta[tid];
    o[tid + 256] = (v1 - mu) * rstd * gamma[tid + 256] + beta[tid + 256];
}

// ---------------------------------------------------------------------------
// Launcher
// ---------------------------------------------------------------------------
extern "C" void kernel_launch(void* const* d_in, const int* in_sizes, int n_in,
                              void* d_out, int out_size) {
    const float* summ   = (const float*)d_in[0];
    const float* dec    = (const float*)d_in[1];
    const float* W_hist = (const float*)d_in[2];
    const float* b_hist = (const float*)d_in[3];
    const float* W1     = (const float*)d_in[4];
    const float* W2     = (const float*)d_in[5];
    const float* W_out  = (const float*)d_in[6];
    const float* b_out  = (const float*)d_in[7];
    const float* gamma  = (const float*)d_in[8];
    const float* beta   = (const float*)d_in[9];
    float* out = (float*)d_out;

    float *bufA, *bufB, *summp;
    cudaGetSymbolAddress((void**)&bufA,  g_bufA);
    cudaGetSymbolAddress((void**)&bufB,  g_bufB);
    cudaGetSymbolAddress((void**)&summp, g_summ);

    // 1) causal running mean -> bufA
    chunk_sum_kernel<<<B_ * NCHUNK, D_>>>(dec);
    chunk_prefix_kernel<<<B_, D_>>>();
    cum_mean_kernel<<<B_ * NCHUNK, D_>>>(dec);

    // 2) summ_proj (tiny)
    summ_proj_kernel<<<B_, D_>>>(summ, W1);

    // 3) GEMM chain
    dim3 grid(D_ / BN, M_TOTAL / BM);   // (4, 256)
    gemm_kernel<0><<<grid, 256>>>(bufA, W_hist, b_hist, nullptr, bufB); // H = tanh(hm@W_hist+b)
    gemm_kernel<1><<<grid, 256>>>(bufB, W2, nullptr, summp, bufA);      // T2 = summ_proj - H@W2
    gemm_kernel<2><<<grid, 256>>>(bufA, W_out, b_out, dec, bufB);       // x = tanh(T2@W_out+b)+dec

    // 4) LayerNorm -> output
    layernorm_kernel<<<M_TOTAL, 256>>>(bufB, gamma, beta, out);
}

// round 3
// speedup vs baseline: 1.9877x; 1.9877x over previous
#include <cuda_runtime.h>
#include <math.h>
#include <stdint.h>

// ---------------------------------------------------------------------------
// Problem constants
// ---------------------------------------------------------------------------
#define B_ 8
#define T_ 4096
#define D_ 512
#define M_TOTAL (B_ * T_)          // 32768
#define CHUNK 128
#define NCHUNK (T_ / CHUNK)        // 32

// ---------------------------------------------------------------------------
// Scratch (no allocation allowed)
// ---------------------------------------------------------------------------
__device__ float g_bufA[(size_t)M_TOTAL * D_];   // 64 MB
__device__ float g_bufB[(size_t)M_TOTAL * D_];   // 64 MB
__device__ float g_partial[B_ * NCHUNK * D_];
__device__ float g_summ[B_ * D_];
__device__ float g_Wt[3 * (size_t)D_ * D_];      // transposed tf32 weights

// ---------------------------------------------------------------------------
// Helpers
// ---------------------------------------------------------------------------
__device__ __forceinline__ float to_tf32(float x) {
    uint32_t u; asm("cvt.rna.tf32.f32 %0, %1;" : "=r"(u) : "f"(x));
    return __uint_as_float(u);
}

__device__ __forceinline__ void mma_tf32_16x8x8(float* d, const uint32_t* a,
                                                const uint32_t* b) {
    asm volatile(
        "mma.sync.aligned.m16n8k8.row.col.f32.tf32.tf32.f32 "
        "{%0,%1,%2,%3}, {%4,%5,%6,%7}, {%8,%9}, {%0,%1,%2,%3};"
        : "+f"(d[0]), "+f"(d[1]), "+f"(d[2]), "+f"(d[3])
        : "r"(a[0]), "r"(a[1]), "r"(a[2]), "r"(a[3]),
          "r"(b[0]), "r"(b[1]));
}

// ---------------------------------------------------------------------------
// Stage 1: causal running mean (chunked scan) -> g_bufA (tf32-rounded)
// ---------------------------------------------------------------------------
__global__ void chunk_sum_kernel(const float* __restrict__ dec) {
    int bc = blockIdx.x;
    int b = bc / NCHUNK, c = bc % NCHUNK;
    int d = threadIdx.x;
    const float* p = dec + ((size_t)(b * T_ + c * CHUNK)) * D_ + d;
    float s = 0.f;
    #pragma unroll 8
    for (int t = 0; t < CHUNK; ++t) s += p[(size_t)t * D_];
    g_partial[(size_t)bc * D_ + d] = s;
}

__global__ void chunk_prefix_kernel() {
    int b = blockIdx.x, d = threadIdx.x;
    float run = 0.f;
    for (int c = 0; c < NCHUNK; ++c) {
        size_t idx = ((size_t)(b * NCHUNK + c)) * D_ + d;
        float v = g_partial[idx];
        g_partial[idx] = run;
        run += v;
    }
}

__global__ void cum_mean_kernel(const float* __restrict__ dec) {
    int bc = blockIdx.x;
    int b = bc / NCHUNK, c = bc % NCHUNK;
    int d = threadIdx.x;
    size_t base = ((size_t)(b * T_ + c * CHUNK)) * D_ + d;
    float run = g_partial[(size_t)bc * D_ + d];
    for (int t = 0; t < CHUNK; ++t) {
        run += dec[base + (size_t)t * D_];
        g_bufA[base + (size_t)t * D_] = to_tf32(run / (float)(c * CHUNK + t + 1));
    }
}

// ---------------------------------------------------------------------------
// Stage 2: summ_proj = summarization @ W1 (tiny)
// ---------------------------------------------------------------------------
__global__ __launch_bounds__(512)
void summ_proj_kernel(const float* __restrict__ summ, const float* __restrict__ W1) {
    __shared__ float s[D_];
    __shared__ float red[4][128];
    int b = blockIdx.y;
    int n0 = blockIdx.x * 128;
    int tid = threadIdx.x;
    int nl = tid & 127;
    int kg = tid >> 7;
    for (int i = tid; i < D_; i += 512) s[i] = summ[b * D_ + i];
    __syncthreads();
    float acc = 0.f;
    int k0 = kg * 128;
    #pragma unroll 8
    for (int k = 0; k < 128; ++k)
        acc = fmaf(s[k0 + k], W1[(size_t)(k0 + k) * D_ + n0 + nl], acc);
    red[kg][nl] = acc;
    __syncthreads();
    if (kg == 0)
        g_summ[b * D_ + n0 + nl] = red[0][nl] + red[1][nl] + red[2][nl] + red[3][nl];
}

// ---------------------------------------------------------------------------
// Weight transpose + tf32 rounding: Wt[n][k] = tf32(W[k][n])
// ---------------------------------------------------------------------------
__global__ void transpose_tf32_kernel(const float* __restrict__ W, float* __restrict__ Wt) {
    __shared__ float t[32][33];
    int bx = blockIdx.x * 32, by = blockIdx.y * 32;
    int x = threadIdx.x, y = threadIdx.y;       // 32 x 8
    #pragma unroll
    for (int i = 0; i < 32; i += 8)
        t[y + i][x] = W[(size_t)(by + y + i) * D_ + bx + x];
    __syncthreads();
    #pragma unroll
    for (int i = 0; i < 32; i += 8)
        Wt[(size_t)(bx + y + i) * D_ + by + x] = to_tf32(t[x][y + i]);
}

// ---------------------------------------------------------------------------
// Stage 3: mma.sync tf32 GEMM  C[M,N] = epilogue(A[M,K] @ Wt[N,K]^T)
//   MODE 0: C = tf32(tanh(acc + bias[col]))
//   MODE 1: C = tf32(summ_proj[b][col] - acc)
//   MODE 2: C = tanh(acc + bias[col]) + resid[row][col]   (fp32)
//
// Tile 128x128, BK=32, 256 threads = 8 warps (4 m x 2 n), warp tile 32x64.
// SMEM tiles stored [row][k] with k-interleave slot = (k&3)*2 | (k>>2)
// within each k8 group so every fragment pair is one LDS.64.
// ---------------------------------------------------------------------------
#define GM_THREADS 256
#define TILE_M 128
#define TILE_N 128
#define BK 32
#define NST (D_ / BK)              // 16
#define RS 40                      // smem row stride in floats (pad)

#define SM_VEC 0                   // 128 floats
#define SM_A   1024
#define TILE_BYTES (128 * RS * 4)  // 20480
#define SM_B   (SM_A + 2 * TILE_BYTES)
#define GEMM_SMEM (SM_B + 2 * TILE_BYTES)   // 82944

template <int MODE>
__global__ __launch_bounds__(GM_THREADS)
void tc_gemm(const float* __restrict__ A, const float* __restrict__ Bt,
             const float* __restrict__ vec, const float* __restrict__ resid,
             float* __restrict__ C) {
    extern __shared__ char smem[];
    float* sv = (float*)(smem + SM_VEC);

    const int tid = threadIdx.x;
    const int wid = tid >> 5, lane = tid & 31;
    const int row0 = blockIdx.y * TILE_M;
    const int col0 = blockIdx.x * TILE_N;
    const int warp_m = wid & 3;        // 0..3 -> 32 rows each
    const int warp_n = wid >> 2;       // 0..1 -> 64 cols each
    const int wm = warp_m * 32;
    const int wn = warp_n * 64;
    const int lq = lane >> 2;          // 0..7
    const int lr = lane & 3;           // 0..3

    // epilogue vector slice -> smem
    {
        const float* v = (MODE == 1) ? (vec + (size_t)(row0 / T_) * D_ + col0)
                                     : (vec + col0);
        for (int i = tid; i < TILE_N; i += GM_THREADS) sv[i] = v[i];
    }

    // global load mapping: each thread owns 4 float4 per tile per stage
    // f = tid + i*256 ; row = f>>3 ; kq = f&7  (32 floats = 8 float4 / row)
    const float* Ab = A + (size_t)row0 * D_;
    const float* Bb = Bt + (size_t)col0 * D_;

    float4 pa[4], pb[4];
    // prologue: load stage 0
    #pragma unroll
    for (int i = 0; i < 4; ++i) {
        int f = tid + i * 256;
        pa[i] = *(const float4*)(Ab + (size_t)(f >> 3) * D_ + (f & 7) * 4);
        pb[i] = *(const float4*)(Bb + (size_t)(f >> 3) * D_ + (f & 7) * 4);
    }

    // STS with k-interleave into buffer `buf`
    auto sts_tiles = [&](int buf, const float4* va, const float4* vb) {
        float* sa = (float*)(smem + SM_A + buf * TILE_BYTES);
        float* sb = (float*)(smem + SM_B + buf * TILE_BYTES);
        #pragma unroll
        for (int i = 0; i < 4; ++i) {
            int f = tid + i * 256;
            int row = f >> 3;
            int kb = (f & 7) * 4;                 // k base 0..28
            const float* ea = (const float*)&va[i];
            const float* eb = (const float*)&vb[i];
            #pragma unroll
            for (int j = 0; j < 4; ++j) {
                int k = kb + j;
                int g = k >> 3, kk = k & 7;
                int slot = ((kk & 3) << 1) | (kk >> 2);
                int col = (g << 3) | slot;
                sa[row * RS + col] = ea[j];
                sb[row * RS + col] = eb[j];
            }
        }
    };

    sts_tiles(0, pa, pb);
    __syncthreads();

    float acc[2][8][4];
    #pragma unroll
    for (int mt = 0; mt < 2; ++mt)
        #pragma unroll
        for (int nt = 0; nt < 8; ++nt)
            #pragma unroll
            for (int j = 0; j < 4; ++j) acc[mt][nt][j] = 0.f;

    for (int s = 0; s < NST; ++s) {
        const int buf = s & 1;
        // prefetch next stage to registers
        if (s + 1 < NST) {
            const float* An = Ab + (s + 1) * BK;
            const float* Bn = Bb + (s + 1) * BK;
            #pragma unroll
            for (int i = 0; i < 4; ++i) {
                int f = tid + i * 256;
                pa[i] = *(const float4*)(An + (size_t)(f >> 3) * D_ + (f & 7) * 4);
                pb[i] = *(const float4*)(Bn + (size_t)(f >> 3) * D_ + (f & 7) * 4);
            }
        }

        const float* sa = (const float*)(smem + SM_A + buf * TILE_BYTES);
        const float* sb = (const float*)(smem + SM_B + buf * TILE_BYTES);

        #pragma unroll
        for (int g = 0; g < 4; ++g) {
            uint32_t af[2][4];
            #pragma unroll
            for (int mt = 0; mt < 2; ++mt) {
                int r = wm + mt * 16 + lq;
                float2 a02 = *(const float2*)&sa[r * RS + g * 8 + lr * 2];
                float2 a13 = *(const float2*)&sa[(r + 8) * RS + g * 8 + lr * 2];
                af[mt][0] = __float_as_uint(a02.x);
                af[mt][1] = __float_as_uint(a13.x);
                af[mt][2] = __float_as_uint(a02.y);
                af[mt][3] = __float_as_uint(a13.y);
            }
            #pragma unroll
            for (int nt = 0; nt < 8; ++nt) {
                int n = wn + nt * 8 + lq;
                float2 b01 = *(const float2*)&sb[n * RS + g * 8 + lr * 2];
                uint32_t bf[2] = { __float_as_uint(b01.x), __float_as_uint(b01.y) };
                mma_tf32_16x8x8(acc[0][nt], af[0], bf);
                mma_tf32_16x8x8(acc[1][nt], af[1], bf);
            }
        }

        if (s + 1 < NST) sts_tiles(buf ^ 1, pa, pb);
        __syncthreads();
    }

    // Epilogue
    #pragma unroll
    for (int mt = 0; mt < 2; ++mt) {
        int row = row0 + wm + mt * 16 + lq;
        #pragma unroll
        for (int nt = 0; nt < 8; ++nt) {
            int col = wn + nt * 8 + lr * 2;     // local col (0..127)
            float c0 = acc[mt][nt][0], c1 = acc[mt][nt][1];
            float c2 = acc[mt][nt][2], c3 = acc[mt][nt][3];
            float2 o0, o1;
            if (MODE == 0) {
                o0.x = to_tf32(tanhf(c0 + sv[col]));
                o0.y = to_tf32(tanhf(c1 + sv[col + 1]));
                o1.x = to_tf32(tanhf(c2 + sv[col]));
                o1.y = to_tf32(tanhf(c3 + sv[col + 1]));
            } else if (MODE == 1) {
                o0.x = to_tf32(sv[col] - c0);
                o0.y = to_tf32(sv[col + 1] - c1);
                o1.x = to_tf32(sv[col] - c2);
                o1.y = to_tf32(sv[col + 1] - c3);
            } else {
                const float* r0p = resid + (size_t)row * D_ + col0 + col;
                const float* r1p = resid + (size_t)(row + 8) * D_ + col0 + col;
                o0.x = tanhf(c0 + sv[col])     + r0p[0];
                o0.y = tanhf(c1 + sv[col + 1]) + r0p[1];
                o1.x = tanhf(c2 + sv[col])     + r1p[0];
                o1.y = tanhf(c3 + sv[col + 1]) + r1p[1];
            }
            *(float2*)(C + (size_t)row * D_ + col0 + col) = o0;
            *(float2*)(C + (size_t)(row + 8) * D_ + col0 + col) = o1;
        }
    }
}

// ---------------------------------------------------------------------------
// Stage 4: LayerNorm (D=512), one block per row
// ---------------------------------------------------------------------------
__global__ __launch_bounds__(256)
void layernorm_kernel(const float* __restrict__ X,
                      const float* __restrict__ gamma,
                      const float* __restrict__ beta,
                      float* __restrict__ out) {
    int row = blockIdx.x;
    const float* x = X + (size_t)row * D_;
    int tid = threadIdx.x;

    float v0 = x[tid];
    float v1 = x[tid + 256];
    float s = v0 + v1;
    float sq = v0 * v0 + v1 * v1;

    __shared__ float redS[8], redQ[8];
    #pragma unroll
    for (int o = 16; o > 0; o >>= 1) {
        s  += __shfl_down_sync(0xffffffffu, s, o);
        sq += __shfl_down_sync(0xffffffffu, sq, o);
    }
    if ((tid & 31) == 0) { redS[tid >> 5] = s; redQ[tid >> 5] = sq; }
    __syncthreads();
    if (tid < 32) {
        float a = (tid < 8) ? redS[tid] : 0.f;
        float b = (tid < 8) ? redQ[tid] : 0.f;
        #pragma unroll
        for (int o = 4; o > 0; o >>= 1) {
            a += __shfl_down_sync(0xffffffffu, a, o);
            b += __shfl_down_sync(0xffffffffu, b, o);
        }
        if (tid == 0) { redS[0] = a; redQ[0] = b; }
    }
    __syncthreads();

    float mu = redS[0] * (1.0f / D_);
    float var = redQ[0] * (1.0f / D_) - mu * mu;
    float rstd = rsqrtf(var + 1e-6f);

    float* o = out + (size_t)row * D_;
    o[tid]       = (v0 - mu) * rstd * gamma[tid] + beta[tid];
    o[tid + 256] = (v1 - mu) * rstd * gamma[tid + 256] + beta[tid + 256];
}

// ---------------------------------------------------------------------------
// Launcher
// ---------------------------------------------------------------------------
extern "C" void kernel_launch(void* const* d_in, const int* in_sizes, int n_in,
                              void* d_out, int out_size) {
    const float* summ   = (const float*)d_in[0];
    const float* dec    = (const float*)d_in[1];
    const float* W_hist = (const float*)d_in[2];
    const float* b_hist = (const float*)d_in[3];
    const float* W1     = (const float*)d_in[4];
    const float* W2     = (const float*)d_in[5];
    const float* W_out  = (const float*)d_in[6];
    const float* b_out  = (const float*)d_in[7];
    const float* gamma  = (const float*)d_in[8];
    const float* beta   = (const float*)d_in[9];
    float* out = (float*)d_out;

    float *bufA, *bufB, *summp, *wt;
    cudaGetSymbolAddress((void**)&bufA,  g_bufA);
    cudaGetSymbolAddress((void**)&bufB,  g_bufB);
    cudaGetSymbolAddress((void**)&summp, g_summ);
    cudaGetSymbolAddress((void**)&wt,    g_Wt);
    float* WtHist = wt;
    float* WtW2   = wt + (size_t)D_ * D_;
    float* WtOut  = wt + 2 * (size_t)D_ * D_;

    cudaFuncSetAttribute(tc_gemm<0>, cudaFuncAttributeMaxDynamicSharedMemorySize, GEMM_SMEM);
    cudaFuncSetAttribute(tc_gemm<1>, cudaFuncAttributeMaxDynamicSharedMemorySize, GEMM_SMEM);
    cudaFuncSetAttribute(tc_gemm<2>, cudaFuncAttributeMaxDynamicSharedMemorySize, GEMM_SMEM);

    // Weight transposes (tf32-rounded) + tiny summ projection
    dim3 tgrid(16, 16), tblk(32, 8);
    transpose_tf32_kernel<<<tgrid, tblk>>>(W_hist, WtHist);
    transpose_tf32_kernel<<<tgrid, tblk>>>(W2,     WtW2);
    transpose_tf32_kernel<<<tgrid, tblk>>>(W_out,  WtOut);
    summ_proj_kernel<<<dim3(4, 8), 512>>>(summ, W1);

    // Causal running mean -> bufA (tf32)
    chunk_sum_kernel<<<B_ * NCHUNK, D_>>>(dec);
    chunk_prefix_kernel<<<B_, D_>>>();
    cum_mean_kernel<<<B_ * NCHUNK, D_>>>(dec);

    // GEMM chain on tensor cores (mma.sync tf32)
    dim3 ggrid(D_ / TILE_N, M_TOTAL / TILE_M);   // (4, 256)
    tc_gemm<0><<<ggrid, GM_THREADS, GEMM_SMEM>>>(bufA, WtHist, b_hist, nullptr, bufB);
    tc_gemm<1><<<ggrid, GM_THREADS, GEMM_SMEM>>>(bufB, WtW2,   summp,  nullptr, bufA);
    tc_gemm<2><<<ggrid, GM_THREADS, GEMM_SMEM>>>(bufA, WtOut,  b_out,  dec,     bufB);

    // LayerNorm -> output
    layernorm_kernel<<<M_TOTAL, 256>>>(bufB, gamma, beta, out);
}

// round 4
// speedup vs baseline: 2.6732x; 1.3449x over previous
#include <cuda_runtime.h>
#include <math.h>
#include <stdint.h>

// ---------------------------------------------------------------------------
// Problem constants
// ---------------------------------------------------------------------------
#define B_ 8
#define T_ 4096
#define D_ 512
#define M_TOTAL (B_ * T_)          // 32768
#define CHUNK 128
#define NCHUNK (T_ / CHUNK)        // 32
#define NST 16                     // k-stages per 512 (BK=32)

// ---------------------------------------------------------------------------
// Scratch
// ---------------------------------------------------------------------------
__device__ float g_bufA[(size_t)M_TOTAL * D_];   // 64 MB (interleaved layout)
__device__ float g_bufB[(size_t)M_TOTAL * D_];   // 64 MB
__device__ float g_partial[B_ * NCHUNK * D_];
__device__ float g_summ[B_ * D_];
__device__ float g_Wt[3 * (size_t)D_ * D_];      // transposed+interleaved tf32 weights

// ---------------------------------------------------------------------------
// Helpers
// ---------------------------------------------------------------------------
__device__ __forceinline__ uint32_t smem_u32(const void* p) {
    uint32_t a;
    asm("{ .reg .u64 t; cvta.to.shared.u64 t, %1; cvt.u32.u64 %0, t; }"
        : "=r"(a) : "l"(p));
    return a;
}
__device__ __forceinline__ float to_tf32(float x) {
    uint32_t u; asm("cvt.rna.tf32.f32 %0, %1;" : "=r"(u) : "f"(x));
    return __uint_as_float(u);
}
__device__ __forceinline__ void mma_tf32_16x8x8(float* d, const uint32_t* a,
                                                const uint32_t* b) {
    asm volatile(
        "mma.sync.aligned.m16n8k8.row.col.f32.tf32.tf32.f32 "
        "{%0,%1,%2,%3}, {%4,%5,%6,%7}, {%8,%9}, {%0,%1,%2,%3};"
        : "+f"(d[0]), "+f"(d[1]), "+f"(d[2]), "+f"(d[3])
        : "r"(a[0]), "r"(a[1]), "r"(a[2]), "r"(a[3]),
          "r"(b[0]), "r"(b[1]));
}

#define CP_ASYNC16(dst, src) \
    asm volatile("cp.async.cg.shared.global [%0], [%1], 16;" \
                 :: "r"(dst), "l"(src) : "memory")
#define CP_COMMIT() asm volatile("cp.async.commit_group;" ::: "memory")
#define CP_WAIT1()  asm volatile("cp.async.wait_group 1;" ::: "memory")
#define CP_WAIT0()  asm volatile("cp.async.wait_group 0;" ::: "memory")

// Interleaved operand layout: element (m, k) of a [rows x 512] matrix lives at
//   ((tile(m)*16 + k>>5)*128 + (m&127))*32 + (kgrp<<3 | slot)
// slot = ((k&3)<<1)|((k&7)>>2): makes (k, k+4) adjacent -> fragment LDS.64.
__device__ __forceinline__ size_t ileave_off(int m, int k) {
    int kk = k & 31;
    int slot = (((kk & 3) << 1) | ((kk & 7) >> 2)) + ((kk >> 3) << 3);
    return ((size_t)((m >> 7) * NST + (k >> 5)) * 128 + (m & 127)) * 32 + slot;
}

// ---------------------------------------------------------------------------
// Stage 1: causal running mean -> g_bufA (tf32, interleaved)
// ---------------------------------------------------------------------------
__global__ void chunk_sum_kernel(const float* __restrict__ dec) {
    int bc = blockIdx.x;
    int b = bc / NCHUNK, c = bc % NCHUNK;
    int d = threadIdx.x;
    const float* p = dec + ((size_t)(b * T_ + c * CHUNK)) * D_ + d;
    float s = 0.f;
    #pragma unroll 8
    for (int t = 0; t < CHUNK; ++t) s += p[(size_t)t * D_];
    g_partial[(size_t)bc * D_ + d] = s;
}

__global__ void chunk_prefix_kernel() {
    int b = blockIdx.x, d = threadIdx.x;
    float run = 0.f;
    for (int c = 0; c < NCHUNK; ++c) {
        size_t idx = ((size_t)(b * NCHUNK + c)) * D_ + d;
        float v = g_partial[idx];
        g_partial[idx] = run;
        run += v;
    }
}

__global__ void cum_mean_kernel(const float* __restrict__ dec) {
    int bc = blockIdx.x;
    int b = bc / NCHUNK, c = bc % NCHUNK;
    int d = threadIdx.x;
    size_t base = ((size_t)(b * T_ + c * CHUNK)) * D_ + d;
    float run = g_partial[(size_t)bc * D_ + d];
    // interleaved output: m = b*T_ + c*CHUNK + t  -> tile = b*32+c, r = t
    int kk = d & 31;
    int slot = (((kk & 3) << 1) | ((kk & 7) >> 2)) + ((kk >> 3) << 3);
    size_t obase = ((size_t)((b * NCHUNK + c) * NST + (d >> 5)) * 128) * 32 + slot;
    for (int t = 0; t < CHUNK; ++t) {
        run += dec[base + (size_t)t * D_];
        g_bufA[obase + (size_t)t * 32] = to_tf32(run / (float)(c * CHUNK + t + 1));
    }
}

// ---------------------------------------------------------------------------
// Stage 2: summ_proj = summarization @ W1 (tiny, plain layout)
// ---------------------------------------------------------------------------
__global__ __launch_bounds__(512)
void summ_proj_kernel(const float* __restrict__ summ, const float* __restrict__ W1) {
    __shared__ float s[D_];
    __shared__ float red[4][128];
    int b = blockIdx.y;
    int n0 = blockIdx.x * 128;
    int tid = threadIdx.x;
    int nl = tid & 127;
    int kg = tid >> 7;
    for (int i = tid; i < D_; i += 512) s[i] = summ[b * D_ + i];
    __syncthreads();
    float acc = 0.f;
    int k0 = kg * 128;
    #pragma unroll 8
    for (int k = 0; k < 128; ++k)
        acc = fmaf(s[k0 + k], W1[(size_t)(k0 + k) * D_ + n0 + nl], acc);
    red[kg][nl] = acc;
    __syncthreads();
    if (kg == 0)
        g_summ[b * D_ + n0 + nl] = red[0][nl] + red[1][nl] + red[2][nl] + red[3][nl];
}

// ---------------------------------------------------------------------------
// Weight transpose + tf32 + interleave: Wt(n,k) = tf32(W[k][n])
// ---------------------------------------------------------------------------
__global__ void transpose_tf32_kernel(const float* __restrict__ W, float* __restrict__ Wt) {
    __shared__ float t[32][33];
    int bx = blockIdx.x * 32, by = blockIdx.y * 32;
    int x = threadIdx.x, y = threadIdx.y;       // 32 x 8
    #pragma unroll
    for (int i = 0; i < 32; i += 8)
        t[y + i][x] = W[(size_t)(by + y + i) * D_ + bx + x];
    __syncthreads();
    #pragma unroll
    for (int i = 0; i < 32; i += 8)
        Wt[ileave_off(bx + y + i, by + x)] = to_tf32(t[x][y + i]);
}

// ---------------------------------------------------------------------------
// Stage 3: mma.sync tf32 GEMM on interleaved operands, cp.async pipeline.
//   MODE 0: C(il) = tf32(tanh(acc + bias[col]))
//   MODE 1: C(il) = tf32(summ_proj[b][col] - acc)
//   MODE 2: C plain = tanh(acc + bias[col]) + resid[row][col]
// Tile 128x128, BK=32, 256 threads = 8 warps (4m x 2n), warp tile 32x64.
// ---------------------------------------------------------------------------
#define GM_THREADS 256
#define TILE_M 128
#define TILE_N 128
#define RS 40                          // smem row stride (floats): conflict-free

#define SM_VEC 0                       // 128 floats
#define SM_A   1024
#define STG_BYTES (128 * RS * 4)       // 20480 per buffer
#define SM_B   (SM_A + 2 * STG_BYTES)  // 41984
#define GEMM_SMEM (SM_B + 2 * STG_BYTES)  // 82944

template <int MODE>
__global__ __launch_bounds__(GM_THREADS, 2)
void tc_gemm(const float* __restrict__ A, const float* __restrict__ Bt,
             const float* __restrict__ vec, const float* __restrict__ resid,
             float* __restrict__ C) {
    extern __shared__ char smem[];
    const uint32_t sbase = smem_u32(smem);
    float* sv = (float*)(smem + SM_VEC);

    const int tid = threadIdx.x;
    const int wid = tid >> 5, lane = tid & 31;
    const int row0 = blockIdx.y * TILE_M;
    const int col0 = blockIdx.x * TILE_N;
    const int wm = (wid & 3) * 32;
    const int wn = (wid >> 2) * 64;
    const int lq = lane >> 2;          // 0..7
    const int lr = lane & 3;           // 0..3

    {
        const float* v = (MODE == 1) ? (vec + (size_t)(row0 / T_) * D_ + col0)
                                     : (vec + col0);
        for (int i = tid; i < TILE_N; i += GM_THREADS) sv[i] = v[i];
    }

    // interleaved tile bases: one stage = contiguous 4096 floats
    const char* Ab = (const char*)(A + (size_t)blockIdx.y * NST * 4096);
    const char* Bb = (const char*)(Bt + (size_t)blockIdx.x * NST * 4096);

    // cp.async mapping: f = tid + i*256 (float4 units); row=f>>3, quad=f&7
    const int frow = tid >> 3;
    const int fq16 = (tid & 7) * 16;

    auto issue_stage = [&](int s, int buf) {
        const char* as = Ab + (size_t)s * 16384;
        const char* bs = Bb + (size_t)s * 16384;
        uint32_t da = sbase + SM_A + buf * STG_BYTES + frow * 160 + fq16;
        uint32_t db = sbase + SM_B + buf * STG_BYTES + frow * 160 + fq16;
        const char* sa = as + ((size_t)frow * 32 + (tid & 7) * 4) * 4;
        const char* sb = bs + ((size_t)frow * 32 + (tid & 7) * 4) * 4;
        #pragma unroll
        for (int i = 0; i < 4; ++i) {
            CP_ASYNC16(da + i * 32 * 160, sa + (size_t)i * 32 * 128);
            CP_ASYNC16(db + i * 32 * 160, sb + (size_t)i * 32 * 128);
        }
    };

    float acc[2][8][4];
    #pragma unroll
    for (int mt = 0; mt < 2; ++mt)
        #pragma unroll
        for (int nt = 0; nt < 8; ++nt)
            #pragma unroll
            for (int j = 0; j < 4; ++j) acc[mt][nt][j] = 0.f;

    issue_stage(0, 0);
    CP_COMMIT();

    #pragma unroll 2
    for (int s = 0; s < NST; ++s) {
        const int buf = s & 1;
        __syncthreads();                       // buf^1 free (compute s-1 done)
        if (s + 1 < NST) {
            issue_stage(s + 1, buf ^ 1);
            CP_COMMIT();
            CP_WAIT1();                        // stage s complete
        } else {
            CP_WAIT0();
        }
        __syncthreads();                       // all threads' copies visible

        const float* sa = (const float*)(smem + SM_A + buf * STG_BYTES);
        const float* sb = (const float*)(smem + SM_B + buf * STG_BYTES);

        #pragma unroll
        for (int g = 0; g < 4; ++g) {
            uint32_t af[2][4];
            #pragma unroll
            for (int mt = 0; mt < 2; ++mt) {
                int r = wm + mt * 16 + lq;
                float2 a02 = *(const float2*)&sa[r * RS + g * 8 + lr * 2];
                float2 a13 = *(const float2*)&sa[(r + 8) * RS + g * 8 + lr * 2];
                af[mt][0] = __float_as_uint(a02.x);
                af[mt][1] = __float_as_uint(a13.x);
                af[mt][2] = __float_as_uint(a02.y);
                af[mt][3] = __float_as_uint(a13.y);
            }
            #pragma unroll
            for (int nt = 0; nt < 8; ++nt) {
                int n = wn + nt * 8 + lq;
                float2 b01 = *(const float2*)&sb[n * RS + g * 8 + lr * 2];
                uint32_t bf[2] = { __float_as_uint(b01.x), __float_as_uint(b01.y) };
                mma_tf32_16x8x8(acc[0][nt], af[0], bf);
                mma_tf32_16x8x8(acc[1][nt], af[1], bf);
            }
        }
    }

    // ---------------- Epilogue ----------------
    if (MODE == 2) {
        #pragma unroll
        for (int mt = 0; mt < 2; ++mt) {
            int row = row0 + wm + mt * 16 + lq;
            #pragma unroll
            for (int nt = 0; nt < 8; ++nt) {
                int col = wn + nt * 8 + lr * 2;
                float c0 = acc[mt][nt][0], c1 = acc[mt][nt][1];
                float c2 = acc[mt][nt][2], c3 = acc[mt][nt][3];
                const float* r0p = resid + (size_t)row * D_ + col0 + col;
                const float* r1p = resid + (size_t)(row + 8) * D_ + col0 + col;
                float2 o0, o1;
                o0.x = tanhf(c0 + sv[col])     + r0p[0];
                o0.y = tanhf(c1 + sv[col + 1]) + r0p[1];
                o1.x = tanhf(c2 + sv[col])     + r1p[0];
                o1.y = tanhf(c3 + sv[col + 1]) + r1p[1];
                *(float2*)(C + (size_t)row * D_ + col0 + col) = o0;
                *(float2*)(C + (size_t)(row + 8) * D_ + col0 + col) = o1;
            }
        }
    } else {
        // interleaved output (feeds the next GEMM as A)
        const size_t tilebase = (size_t)blockIdx.y * NST * 4096;
        #pragma unroll
        for (int mt = 0; mt < 2; ++mt) {
            int r = wm + mt * 16 + lq;
            #pragma unroll
            for (int nt = 0; nt < 8; ++nt) {
                int col = wn + nt * 8 + lr * 2;       // local col 0..127
                int k = col0 + col;
                int kk = k & 31;
                int slot = (((kk & 3) << 1) | ((kk & 7) >> 2)) + ((kk >> 3) << 3);
                size_t off = tilebase + (size_t)(k >> 5) * 4096 + (size_t)r * 32 + slot;
                float c0 = acc[mt][nt][0], c1 = acc[mt][nt][1];
                float c2 = acc[mt][nt][2], c3 = acc[mt][nt][3];
                float v0, v1, v2, v3;
                if (MODE == 0) {
                    v0 = to_tf32(tanhf(c0 + sv[col]));
                    v1 = to_tf32(tanhf(c1 + sv[col + 1]));
                    v2 = to_tf32(tanhf(c2 + sv[col]));
                    v3 = to_tf32(tanhf(c3 + sv[col + 1]));
                } else {
                    v0 = to_tf32(sv[col] - c0);
                    v1 = to_tf32(sv[col + 1] - c1);
                    v2 = to_tf32(sv[col] - c2);
                    v3 = to_tf32(sv[col + 1] - c3);
                }
                C[off]       = v0;
                C[off + 2]   = v1;     // k+1 -> slot+2
                C[off + 256] = v2;     // row r+8
                C[off + 258] = v3;
            }
        }
    }
}

// ---------------------------------------------------------------------------
// Stage 4: LayerNorm (D=512), one block per row
// ---------------------------------------------------------------------------
__global__ __launch_bounds__(256)
void layernorm_kernel(const float* __restrict__ X,
                      const float* __restrict__ gamma,
                      const float* __restrict__ beta,
                      float* __restrict__ out) {
    int row = blockIdx.x;
    const float* x = X + (size_t)row * D_;
    int tid = threadIdx.x;

    float v0 = x[tid];
    float v1 = x[tid + 256];
    float s = v0 + v1;
    float sq = v0 * v0 + v1 * v1;

    __shared__ float redS[8], redQ[8];
    #pragma unroll
    for (int o = 16; o > 0; o >>= 1) {
        s  += __shfl_down_sync(0xffffffffu, s, o);
        sq += __shfl_down_sync(0xffffffffu, sq, o);
    }
    if ((tid & 31) == 0) { redS[tid >> 5] = s; redQ[tid >> 5] = sq; }
    __syncthreads();
    if (tid < 32) {
        float a = (tid < 8) ? redS[tid] : 0.f;
        float b = (tid < 8) ? redQ[tid] : 0.f;
        #pragma unroll
        for (int o = 4; o > 0; o >>= 1) {
            a += __shfl_down_sync(0xffffffffu, a, o);
            b += __shfl_down_sync(0xffffffffu, b, o);
        }
        if (tid == 0) { redS[0] = a; redQ[0] = b; }
    }
    __syncthreads();

    float mu = redS[0] * (1.0f / D_);
    float var = redQ[0] * (1.0f / D_) - mu * mu;
    float rstd = rsqrtf(var + 1e-6f);

    float* o = out + (size_t)row * D_;
    o[tid]       = (v0 - mu) * rstd * gamma[tid] + beta[tid];
    o[tid + 256] = (v1 - mu) * rstd * gamma[tid + 256] + beta[tid + 256];
}

// ---------------------------------------------------------------------------
// Launcher
// ---------------------------------------------------------------------------
extern "C" void kernel_launch(void* const* d_in, const int* in_sizes, int n_in,
                              void* d_out, int out_size) {
    const float* summ   = (const float*)d_in[0];
    const float* dec    = (const float*)d_in[1];
    const float* W_hist = (const float*)d_in[2];
    const float* b_hist = (const float*)d_in[3];
    const float* W1     = (const float*)d_in[4];
    const float* W2     = (const float*)d_in[5];
    const float* W_out  = (const float*)d_in[6];
    const float* b_out  = (const float*)d_in[7];
    const float* gamma  = (const float*)d_in[8];
    const float* beta   = (const float*)d_in[9];
    float* out = (float*)d_out;

    float *bufA, *bufB, *summp, *wt;
    cudaGetSymbolAddress((void**)&bufA,  g_bufA);
    cudaGetSymbolAddress((void**)&bufB,  g_bufB);
    cudaGetSymbolAddress((void**)&summp, g_summ);
    cudaGetSymbolAddress((void**)&wt,    g_Wt);
    float* WtHist = wt;
    float* WtW2   = wt + (size_t)D_ * D_;
    float* WtOut  = wt + 2 * (size_t)D_ * D_;

    cudaFuncSetAttribute(tc_gemm<0>, cudaFuncAttributeMaxDynamicSharedMemorySize, GEMM_SMEM);
    cudaFuncSetAttribute(tc_gemm<1>, cudaFuncAttributeMaxDynamicSharedMemorySize, GEMM_SMEM);
    cudaFuncSetAttribute(tc_gemm<2>, cudaFuncAttributeMaxDynamicSharedMemorySize, GEMM_SMEM);

    // Weight transposes (tf32 + interleave) + tiny summ projection
    dim3 tgrid(16, 16), tblk(32, 8);
    transpose_tf32_kernel<<<tgrid, tblk>>>(W_hist, WtHist);
    transpose_tf32_kernel<<<tgrid, tblk>>>(W2,     WtW2);
    transpose_tf32_kernel<<<tgrid, tblk>>>(W_out,  WtOut);
    summ_proj_kernel<<<dim3(4, 8), 512>>>(summ, W1);

    // Causal running mean -> bufA (tf32, interleaved)
    chunk_sum_kernel<<<B_ * NCHUNK, D_>>>(dec);
    chunk_prefix_kernel<<<B_, D_>>>();
    cum_mean_kernel<<<B_ * NCHUNK, D_>>>(dec);

    // GEMM chain on tensor cores (mma.sync tf32, cp.async pipeline)
    dim3 ggrid(D_ / TILE_N, M_TOTAL / TILE_M);   // (4, 256)
    tc_gemm<0><<<ggrid, GM_THREADS, GEMM_SMEM>>>(bufA, WtHist, b_hist, nullptr, bufB);
    tc_gemm<1><<<ggrid, GM_THREADS, GEMM_SMEM>>>(bufB, WtW2,   summp,  nullptr, bufA);
    tc_gemm<2><<<ggrid, GM_THREADS, GEMM_SMEM>>>(bufA, WtOut,  b_out,  dec,     bufB);

    // LayerNorm -> output
    layernorm_kernel<<<M_TOTAL, 256>>>(bufB, gamma, beta, out);
}